// round 1
// baseline (speedup 1.0000x reference)
#include <cuda_runtime.h>
#include <cstdint>
#include <math.h>

// Problem constants
#define TT 256
#define NB 128
#define DD 1024
#define HH 1024
#define G4 4096                 // 4*H
#define NH (NB * HH)            // 131072

// ---------------- scratch (static device memory; no allocation) ----------------
__device__ float g_Gx[(size_t)TT * NB * G4];  // [T*N, 4H] input-projection + bias (512 MB)
__device__ float g_H1[(size_t)TT * NB * HH];  // layer-0 hidden outputs per t (128 MB)
__device__ float g_hA[NH];
__device__ float g_hB[NH];
__device__ float g_c[NH];

// ---------------- tf32 mma helpers ----------------
__device__ __forceinline__ uint32_t f2tf32(float x) {
    uint32_t r;
    asm("cvt.rna.tf32.f32 %0, %1;" : "=r"(r) : "f"(x));
    return r;
}

__device__ __forceinline__ void mma_tf32(float* d,
                                         uint32_t a0, uint32_t a1, uint32_t a2, uint32_t a3,
                                         uint32_t b0, uint32_t b1) {
    asm volatile(
        "mma.sync.aligned.m16n8k8.row.col.f32.tf32.tf32.f32 "
        "{%0,%1,%2,%3}, {%4,%5,%6,%7}, {%8,%9}, {%0,%1,%2,%3};\n"
        : "+f"(d[0]), "+f"(d[1]), "+f"(d[2]), "+f"(d[3])
        : "r"(a0), "r"(a1), "r"(a2), "r"(a3), "r"(b0), "r"(b1));
}

__device__ __forceinline__ float sigm(float x) { return 1.0f / (1.0f + expf(-x)); }

// ============================================================================
// Batched input projection: out[M,4096] = inp[M,1024] @ W[4096,1024]^T + (b_ih+b_hh)
// CTA tile 128(M) x 128(N), K-chunk 32. 256 threads = 8 warps.
// Warp tile 32(M) x 64(N): 2 m16 frags x 8 n8 frags.
// Grid: x = N tiles (32)  [inner, so each wave reuses the A slab in L2],
//       y = M tiles (M/128).
// ============================================================================
__global__ __launch_bounds__(256) void gemm_gx_kernel(
    const float* __restrict__ A,     // [M, 1024]
    const float* __restrict__ W,     // [4096, 1024]
    const float* __restrict__ b_ih,  // [4096]
    const float* __restrict__ b_hh,  // [4096]
    float* __restrict__ out)         // [M, 4096]
{
    __shared__ __align__(16) uint32_t As[128][36];  // pad: row stride 36 (== 4 mod 32)
    __shared__ __align__(16) uint32_t Ws[128][36];

    const int tid  = threadIdx.x;
    const int lane = tid & 31;
    const int warp = tid >> 5;
    const int g    = lane >> 2;   // group id (0..7)
    const int t4   = lane & 3;    // thread-in-group
    const int wm   = warp & 3;    // 0..3 -> m offset wm*32
    const int wn   = warp >> 2;   // 0..1 -> n offset wn*64

    const int n0 = blockIdx.x * 128;
    const int m0 = blockIdx.y * 128;

    float acc[2][8][4];
#pragma unroll
    for (int mi = 0; mi < 2; mi++)
#pragma unroll
        for (int ni = 0; ni < 8; ni++)
#pragma unroll
            for (int p = 0; p < 4; p++) acc[mi][ni][p] = 0.0f;

    for (int k0 = 0; k0 < 1024; k0 += 32) {
        // A tile 128x32 floats = 1024 float4 -> 4 per thread
#pragma unroll
        for (int i = 0; i < 4; i++) {
            int idx = tid + i * 256;
            int row = idx >> 3;
            int c4  = idx & 7;
            float4 v = *(const float4*)(A + (size_t)(m0 + row) * 1024 + k0 + c4 * 4);
            uint4 u;
            u.x = f2tf32(v.x); u.y = f2tf32(v.y); u.z = f2tf32(v.z); u.w = f2tf32(v.w);
            *(uint4*)&As[row][c4 * 4] = u;
        }
        // W tile 128x32 floats = 1024 float4 -> 4 per thread
#pragma unroll
        for (int i = 0; i < 4; i++) {
            int idx = tid + i * 256;
            int row = idx >> 3;
            int c4  = idx & 7;
            float4 v = *(const float4*)(W + (size_t)(n0 + row) * 1024 + k0 + c4 * 4);
            uint4 u;
            u.x = f2tf32(v.x); u.y = f2tf32(v.y); u.z = f2tf32(v.z); u.w = f2tf32(v.w);
            *(uint4*)&Ws[row][c4 * 4] = u;
        }
        __syncthreads();

#pragma unroll
        for (int kk = 0; kk < 32; kk += 8) {
            uint32_t a[2][4];
#pragma unroll
            for (int mi = 0; mi < 2; mi++) {
                int r = wm * 32 + mi * 16;
                a[mi][0] = As[r + g][kk + t4];
                a[mi][1] = As[r + g + 8][kk + t4];
                a[mi][2] = As[r + g][kk + t4 + 4];
                a[mi][3] = As[r + g + 8][kk + t4 + 4];
            }
#pragma unroll
            for (int ni = 0; ni < 8; ni++) {
                int wr = wn * 64 + ni * 8 + g;
                uint32_t b0 = Ws[wr][kk + t4];
                uint32_t b1 = Ws[wr][kk + t4 + 4];
#pragma unroll
                for (int mi = 0; mi < 2; mi++)
                    mma_tf32(acc[mi][ni], a[mi][0], a[mi][1], a[mi][2], a[mi][3], b0, b1);
            }
        }
        __syncthreads();
    }

    // epilogue: add combined bias, write fp32
#pragma unroll
    for (int mi = 0; mi < 2; mi++) {
#pragma unroll
        for (int ni = 0; ni < 8; ni++) {
            int row = m0 + wm * 32 + mi * 16 + g;
            int col = n0 + wn * 64 + ni * 8 + t4 * 2;
            float bias0 = b_ih[col] + b_hh[col];
            float bias1 = b_ih[col + 1] + b_hh[col + 1];
            out[(size_t)row * 4096 + col]           = acc[mi][ni][0] + bias0;
            out[(size_t)row * 4096 + col + 1]       = acc[mi][ni][1] + bias1;
            out[(size_t)(row + 8) * 4096 + col]     = acc[mi][ni][2] + bias0;
            out[(size_t)(row + 8) * 4096 + col + 1] = acc[mi][ni][3] + bias1;
        }
    }
}

// ============================================================================
// One LSTM recurrence step for one layer.
// gates[128,4096] = Gx_t + h_in @ Whh^T ; pointwise -> c, h_out.
// 128 CTAs, CTA b owns 8 hidden units (32 gate columns: i/f/g/o blocks).
// 256 threads = 8 warps; warp w handles rows w*16..w*16+15 (all 128 batch rows).
// c columns are CTA-private across steps -> no race. h double-buffered.
// ============================================================================
__global__ __launch_bounds__(256) void lstm_step_kernel(
    const float* __restrict__ Gx,     // [128, 4096] slice for this t
    const float* __restrict__ Whh,    // [4096, 1024] for this layer
    const float* __restrict__ h_in,   // [128, 1024]
    float* __restrict__ h_out,        // [128, 1024]
    float* __restrict__ c,            // [128, 1024]
    float* __restrict__ h_extra)      // optional duplicate (d_out), may be null
{
    __shared__ __align__(16) uint32_t hs[128][68];  // 64 K-cols, stride 68 (== 4 mod 32)
    __shared__ __align__(16) uint32_t ws[32][68];

    const int tid  = threadIdx.x;
    const int lane = tid & 31;
    const int warp = tid >> 5;
    const int g    = lane >> 2;
    const int t4   = lane & 3;
    const int hu0  = blockIdx.x * 8;  // this CTA's hidden-unit slab

    float acc[4][4];  // [gate][c-frag]
#pragma unroll
    for (int q = 0; q < 4; q++)
#pragma unroll
        for (int p = 0; p < 4; p++) acc[q][p] = 0.0f;

    for (int k0 = 0; k0 < 1024; k0 += 64) {
        // h tile 128x64 floats = 2048 float4 -> 8 per thread
#pragma unroll
        for (int i = 0; i < 8; i++) {
            int idx = tid + i * 256;
            int row = idx >> 4;
            int c4  = idx & 15;
            float4 v = *(const float4*)(h_in + (size_t)row * 1024 + k0 + c4 * 4);
            uint4 u;
            u.x = f2tf32(v.x); u.y = f2tf32(v.y); u.z = f2tf32(v.z); u.w = f2tf32(v.w);
            *(uint4*)&hs[row][c4 * 4] = u;
        }
        // W tile: 32 gate rows (4 gates x 8 units) x 64 cols = 512 float4 -> 2/thread
#pragma unroll
        for (int i = 0; i < 2; i++) {
            int idx = tid + i * 256;
            int row = idx >> 4;  // 0..31 local gate row
            int c4  = idx & 15;
            int grow = (row >> 3) * 1024 + hu0 + (row & 7);  // global W_hh row
            float4 v = *(const float4*)(Whh + (size_t)grow * 1024 + k0 + c4 * 4);
            uint4 u;
            u.x = f2tf32(v.x); u.y = f2tf32(v.y); u.z = f2tf32(v.z); u.w = f2tf32(v.w);
            *(uint4*)&ws[row][c4 * 4] = u;
        }
        __syncthreads();

        const int m0 = warp * 16;
#pragma unroll
        for (int kk = 0; kk < 64; kk += 8) {
            uint32_t a0 = hs[m0 + g][kk + t4];
            uint32_t a1 = hs[m0 + g + 8][kk + t4];
            uint32_t a2 = hs[m0 + g][kk + t4 + 4];
            uint32_t a3 = hs[m0 + g + 8][kk + t4 + 4];
#pragma unroll
            for (int q = 0; q < 4; q++) {
                uint32_t b0 = ws[q * 8 + g][kk + t4];
                uint32_t b1 = ws[q * 8 + g][kk + t4 + 4];
                mma_tf32(acc[q], a0, a1, a2, a3, b0, b1);
            }
        }
        __syncthreads();
    }

    // ---- epilogue: add Gx, pointwise LSTM, write h (and c) ----
    const int r0   = warp * 16 + g;       // rows r0, r0+8
    const int col0 = hu0 + t4 * 2;        // hidden cols col0, col0+1
#pragma unroll
    for (int q = 0; q < 4; q++) {
        int gc = q * 1024 + col0;
        acc[q][0] += Gx[(size_t)r0 * 4096 + gc];
        acc[q][1] += Gx[(size_t)r0 * 4096 + gc + 1];
        acc[q][2] += Gx[(size_t)(r0 + 8) * 4096 + gc];
        acc[q][3] += Gx[(size_t)(r0 + 8) * 4096 + gc + 1];
    }
#pragma unroll
    for (int p = 0; p < 4; p++) {
        int row = r0 + ((p >= 2) ? 8 : 0);
        int col = col0 + (p & 1);
        size_t idx = (size_t)row * 1024 + col;
        float iv = acc[0][p], fv = acc[1][p], gv = acc[2][p], ov = acc[3][p];
        float cold = c[idx];
        float cn = sigm(fv) * cold + sigm(iv) * tanhf(gv);
        float hn = sigm(ov) * tanhf(cn);
        c[idx] = cn;
        h_out[idx] = hn;
        if (h_extra) h_extra[idx] = hn;
    }
}

__global__ void copy_kernel(const float* __restrict__ src, float* __restrict__ dst, int n) {
    int i = blockIdx.x * 256 + threadIdx.x;
    if (i < n) dst[i] = src[i];
}

// ============================================================================
extern "C" void kernel_launch(void* const* d_in, const int* in_sizes, int n_in,
                              void* d_out, int out_size) {
    const float* x    = (const float*)d_in[0];  // [T, N, D]
    const float* h0   = (const float*)d_in[1];  // [L, N, H]
    const float* c0   = (const float*)d_in[2];  // [L, N, H]
    const float* Wih  = (const float*)d_in[3];  // [L, 4H, D]
    const float* Whh  = (const float*)d_in[4];  // [L, 4H, H]
    const float* bih  = (const float*)d_in[5];  // [L, 4H]
    const float* bhh  = (const float*)d_in[6];  // [L, 4H]
    float* out = (float*)d_out;                 // [N, H]

    float *pGx, *pH1, *phA, *phB, *pc;
    cudaGetSymbolAddress((void**)&pGx, g_Gx);
    cudaGetSymbolAddress((void**)&pH1, g_H1);
    cudaGetSymbolAddress((void**)&phA, g_hA);
    cudaGetSymbolAddress((void**)&phB, g_hB);
    cudaGetSymbolAddress((void**)&pc,  g_c);

    const int M = TT * NB;  // 32768

    for (int layer = 0; layer < 2; layer++) {
        const float* inp = (layer == 0) ? x : pH1;
        const float* Wl  = Wih + (size_t)layer * G4 * DD;
        const float* Rl  = Whh + (size_t)layer * G4 * HH;

        // 1) batched input projection + bias -> g_Gx [T*N, 4H]
        dim3 grid_g(G4 / 128, M / 128);
        gemm_gx_kernel<<<grid_g, 256>>>(inp, Wl,
                                        bih + (size_t)layer * G4,
                                        bhh + (size_t)layer * G4, pGx);

        // 2) init cell state for this layer
        copy_kernel<<<NH / 256, 256>>>(c0 + (size_t)layer * NH, pc, NH);

        // 3) recurrence
        for (int t = 0; t < TT; t++) {
            const float* hin;
            float* hout;
            float* hextra = nullptr;
            if (layer == 0) {
                hin  = (t == 0) ? h0 : (pH1 + (size_t)(t - 1) * NH);
                hout = pH1 + (size_t)t * NH;  // becomes layer-1 input
            } else {
                hin  = (t == 0) ? (h0 + NH) : ((t & 1) ? phA : phB);
                hout = (t & 1) ? phB : phA;
                if (t == TT - 1) hextra = out;
            }
            lstm_step_kernel<<<128, 256>>>(pGx + (size_t)t * NB * G4, Rl,
                                           hin, hout, pc, hextra);
        }
    }
}

// round 2
// speedup vs baseline: 1.2905x; 1.2905x over previous
#include <cuda_runtime.h>
#include <cstdint>
#include <math.h>

// Problem constants
#define TT 256
#define NB 128
#define DD 1024
#define HH 1024
#define G4 4096                 // 4*H
#define NH (NB * HH)            // 131072

#define NCTAS 128               // persistent grid size (<=148 SMs, 1 CTA/SM)
#define WS_STRIDE 1028          // W smem row stride (words): bank = (4*row+col)%32
#define HS_STRIDE 68            // h smem row stride (words)

// ---------------- scratch (static device memory; no allocation) ----------------
__device__ float g_Gx[(size_t)TT * NB * G4];  // [T*N, 4H] input projection + bias
__device__ float g_H1[(size_t)TT * NB * HH];  // layer-0 hidden outputs (tf32 bits)
__device__ float g_hA[NH];
__device__ float g_hB[NH];
__device__ float g_c[NH];
__device__ float g_h0c[2 * NH];               // h0 pre-converted to tf32 bits

// grid barrier state
__device__ unsigned g_bar_cnt = 0;
__device__ volatile unsigned g_bar_gen = 0;

// ---------------- helpers ----------------
__device__ __forceinline__ uint32_t f2tf32(float x) {
    uint32_t r;
    asm("cvt.rna.tf32.f32 %0, %1;" : "=r"(r) : "f"(x));
    return r;
}

__device__ __forceinline__ void mma_tf32(float* d,
                                         uint32_t a0, uint32_t a1, uint32_t a2, uint32_t a3,
                                         uint32_t b0, uint32_t b1) {
    asm volatile(
        "mma.sync.aligned.m16n8k8.row.col.f32.tf32.tf32.f32 "
        "{%0,%1,%2,%3}, {%4,%5,%6,%7}, {%8,%9}, {%0,%1,%2,%3};\n"
        : "+f"(d[0]), "+f"(d[1]), "+f"(d[2]), "+f"(d[3])
        : "r"(a0), "r"(a1), "r"(a2), "r"(a3), "r"(b0), "r"(b1));
}

__device__ __forceinline__ float sigm(float x) { return 1.0f / (1.0f + expf(-x)); }

__device__ __forceinline__ void cpasync16(uint32_t* dst_smem, const void* src) {
    uint32_t a = (uint32_t)__cvta_generic_to_shared(dst_smem);
    asm volatile("cp.async.cg.shared.global [%0], [%1], 16;" :: "r"(a), "l"(src));
}
__device__ __forceinline__ void cp_commit() { asm volatile("cp.async.commit_group;"); }
template <int N>
__device__ __forceinline__ void cp_wait() { asm volatile("cp.async.wait_group %0;" :: "n"(N)); }

__device__ __forceinline__ void gsync() {
    __syncthreads();
    if (threadIdx.x == 0) {
        __threadfence();
        unsigned gen = g_bar_gen;
        if (atomicAdd(&g_bar_cnt, 1) == NCTAS - 1) {
            atomicExch(&g_bar_cnt, 0);
            __threadfence();
            g_bar_gen = gen + 1;
        } else {
            while (g_bar_gen == gen) { }
        }
        __threadfence();
    }
    __syncthreads();
}

// ============================================================================
// Batched input projection: out[M,4096] = inp[M,1024] @ W[4096,1024]^T + bias
// (unchanged from round 1; not the current bottleneck)
// ============================================================================
__global__ __launch_bounds__(256) void gemm_gx_kernel(
    const float* __restrict__ A, const float* __restrict__ W,
    const float* __restrict__ b_ih, const float* __restrict__ b_hh,
    float* __restrict__ out)
{
    __shared__ __align__(16) uint32_t As[128][36];
    __shared__ __align__(16) uint32_t Ws[128][36];

    const int tid  = threadIdx.x;
    const int lane = tid & 31;
    const int warp = tid >> 5;
    const int g    = lane >> 2;
    const int t4   = lane & 3;
    const int wm   = warp & 3;
    const int wn   = warp >> 2;

    const int n0 = blockIdx.x * 128;
    const int m0 = blockIdx.y * 128;

    float acc[2][8][4];
#pragma unroll
    for (int mi = 0; mi < 2; mi++)
#pragma unroll
        for (int ni = 0; ni < 8; ni++)
#pragma unroll
            for (int p = 0; p < 4; p++) acc[mi][ni][p] = 0.0f;

    for (int k0 = 0; k0 < 1024; k0 += 32) {
#pragma unroll
        for (int i = 0; i < 4; i++) {
            int idx = tid + i * 256;
            int row = idx >> 3;
            int c4  = idx & 7;
            float4 v = *(const float4*)(A + (size_t)(m0 + row) * 1024 + k0 + c4 * 4);
            uint4 u; u.x = f2tf32(v.x); u.y = f2tf32(v.y); u.z = f2tf32(v.z); u.w = f2tf32(v.w);
            *(uint4*)&As[row][c4 * 4] = u;
        }
#pragma unroll
        for (int i = 0; i < 4; i++) {
            int idx = tid + i * 256;
            int row = idx >> 3;
            int c4  = idx & 7;
            float4 v = *(const float4*)(W + (size_t)(n0 + row) * 1024 + k0 + c4 * 4);
            uint4 u; u.x = f2tf32(v.x); u.y = f2tf32(v.y); u.z = f2tf32(v.z); u.w = f2tf32(v.w);
            *(uint4*)&Ws[row][c4 * 4] = u;
        }
        __syncthreads();

#pragma unroll
        for (int kk = 0; kk < 32; kk += 8) {
            uint32_t a[2][4];
#pragma unroll
            for (int mi = 0; mi < 2; mi++) {
                int r = wm * 32 + mi * 16;
                a[mi][0] = As[r + g][kk + t4];
                a[mi][1] = As[r + g + 8][kk + t4];
                a[mi][2] = As[r + g][kk + t4 + 4];
                a[mi][3] = As[r + g + 8][kk + t4 + 4];
            }
#pragma unroll
            for (int ni = 0; ni < 8; ni++) {
                int wr = wn * 64 + ni * 8 + g;
                uint32_t b0 = Ws[wr][kk + t4];
                uint32_t b1 = Ws[wr][kk + t4 + 4];
#pragma unroll
                for (int mi = 0; mi < 2; mi++)
                    mma_tf32(acc[mi][ni], a[mi][0], a[mi][1], a[mi][2], a[mi][3], b0, b1);
            }
        }
        __syncthreads();
    }

#pragma unroll
    for (int mi = 0; mi < 2; mi++) {
#pragma unroll
        for (int ni = 0; ni < 8; ni++) {
            int row = m0 + wm * 32 + mi * 16 + g;
            int col = n0 + wn * 64 + ni * 8 + t4 * 2;
            float bias0 = b_ih[col] + b_hh[col];
            float bias1 = b_ih[col + 1] + b_hh[col + 1];
            out[(size_t)row * 4096 + col]           = acc[mi][ni][0] + bias0;
            out[(size_t)row * 4096 + col + 1]       = acc[mi][ni][1] + bias1;
            out[(size_t)(row + 8) * 4096 + col]     = acc[mi][ni][2] + bias0;
            out[(size_t)(row + 8) * 4096 + col + 1] = acc[mi][ni][3] + bias1;
        }
    }
}

// ============================================================================
// Persistent recurrence kernel: runs ALL 256 timesteps of one layer.
// 128 CTAs (1/SM, co-resident), CTA b owns hidden units [8b, 8b+8) =
// 32 gate rows. W slab (32x1024 tf32 = 128 KB) loaded to SMEM ONCE.
// h is stored in global as tf32 bits -> raw cp.async double-buffered loads.
// Grid barrier between steps.
// ============================================================================
__global__ __launch_bounds__(256) void lstm_seq_kernel(
    const float* __restrict__ Gx_base,   // [T, 128, 4096]
    const float* __restrict__ Whh,       // [4096, 1024] fp32 (this layer)
    const float* __restrict__ h0c,       // [128,1024] tf32 bits
    float* __restrict__ H1,              // mode0: output sequence (tf32 bits)
    float* __restrict__ hA, float* __restrict__ hB,  // mode1 ping-pong
    float* __restrict__ c,               // [128,1024] fp32
    float* __restrict__ out,             // mode1: final fp32 [128,1024]
    int mode)
{
    extern __shared__ __align__(16) uint32_t sm[];
    uint32_t* ws = sm;                              // [32][WS_STRIDE]
    uint32_t* hs[2];
    hs[0] = sm + 32 * WS_STRIDE;                    // [128][HS_STRIDE]
    hs[1] = hs[0] + 128 * HS_STRIDE;

    const int tid  = threadIdx.x;
    const int lane = tid & 31;
    const int warp = tid >> 5;
    const int g    = lane >> 2;
    const int t4   = lane & 3;
    const int hu0  = blockIdx.x * 8;

    // ---- load W slab once: 32 gate rows x 1024, cvt to tf32 ----
#pragma unroll
    for (int i = 0; i < 32; i++) {
        int idx4 = tid + i * 256;            // float4 index, 0..8191
        int row  = idx4 >> 8;                // 0..31
        int c4   = idx4 & 255;
        int grow = (row >> 3) * 1024 + hu0 + (row & 7);
        float4 v = *(const float4*)(Whh + (size_t)grow * 1024 + c4 * 4);
        uint4 u; u.x = f2tf32(v.x); u.y = f2tf32(v.y); u.z = f2tf32(v.z); u.w = f2tf32(v.w);
        *(uint4*)&ws[(size_t)row * WS_STRIDE + c4 * 4] = u;
    }
    __syncthreads();

    const int ld_row = tid >> 4;   // 0..15 base rows (x8 iters -> 128)
    const int ld_c4  = tid & 15;

    for (int t = 0; t < TT; t++) {
        const uint32_t* hin;
        if (mode == 0)
            hin = (const uint32_t*)(t == 0 ? h0c : H1 + (size_t)(t - 1) * NH);
        else
            hin = (const uint32_t*)(t == 0 ? h0c : ((t & 1) ? hA : hB));

        // prefetch k-tile 0
#pragma unroll
        for (int i = 0; i < 8; i++) {
            int row = ld_row + i * 16;
            cpasync16(&hs[0][(size_t)row * HS_STRIDE + ld_c4 * 4],
                      hin + (size_t)row * 1024 + ld_c4 * 4);
        }
        cp_commit();

        float acc[4][4];
#pragma unroll
        for (int q = 0; q < 4; q++)
#pragma unroll
            for (int p = 0; p < 4; p++) acc[q][p] = 0.0f;

        const int m0 = warp * 16;

        for (int kt = 0; kt < 16; kt++) {
            if (kt < 15) {
                uint32_t* dst = hs[(kt + 1) & 1];
                const uint32_t* src = hin + (size_t)(kt + 1) * 64;
#pragma unroll
                for (int i = 0; i < 8; i++) {
                    int row = ld_row + i * 16;
                    cpasync16(&dst[(size_t)row * HS_STRIDE + ld_c4 * 4],
                              src + (size_t)row * 1024 + ld_c4 * 4);
                }
                cp_commit();
                cp_wait<1>();
            } else {
                cp_wait<0>();
            }
            __syncthreads();

            const uint32_t* hp = hs[kt & 1];
            const int kw = kt * 64;
#pragma unroll
            for (int kk = 0; kk < 64; kk += 8) {
                uint32_t a0 = hp[(size_t)(m0 + g) * HS_STRIDE + kk + t4];
                uint32_t a1 = hp[(size_t)(m0 + g + 8) * HS_STRIDE + kk + t4];
                uint32_t a2 = hp[(size_t)(m0 + g) * HS_STRIDE + kk + t4 + 4];
                uint32_t a3 = hp[(size_t)(m0 + g + 8) * HS_STRIDE + kk + t4 + 4];
#pragma unroll
                for (int q = 0; q < 4; q++) {
                    uint32_t b0 = ws[(size_t)(q * 8 + g) * WS_STRIDE + kw + kk + t4];
                    uint32_t b1 = ws[(size_t)(q * 8 + g) * WS_STRIDE + kw + kk + t4 + 4];
                    mma_tf32(acc[q], a0, a1, a2, a3, b0, b1);
                }
            }
            __syncthreads();
        }

        // ---- epilogue: Gx + pointwise -> c, h ----
        const float* Gx = Gx_base + (size_t)t * NB * G4;
        uint32_t* hout = (uint32_t*)(mode == 0 ? (H1 + (size_t)t * NH)
                                               : ((t & 1) ? hB : hA));
        const int r0   = warp * 16 + g;
        const int col0 = hu0 + t4 * 2;
#pragma unroll
        for (int q = 0; q < 4; q++) {
            int gc = q * 1024 + col0;
            acc[q][0] += Gx[(size_t)r0 * 4096 + gc];
            acc[q][1] += Gx[(size_t)r0 * 4096 + gc + 1];
            acc[q][2] += Gx[(size_t)(r0 + 8) * 4096 + gc];
            acc[q][3] += Gx[(size_t)(r0 + 8) * 4096 + gc + 1];
        }
#pragma unroll
        for (int p = 0; p < 4; p++) {
            int row = r0 + ((p >= 2) ? 8 : 0);
            int col = col0 + (p & 1);
            size_t idx = (size_t)row * 1024 + col;
            float iv = acc[0][p], fv = acc[1][p], gv = acc[2][p], ov = acc[3][p];
            float cold = c[idx];
            float cn = sigm(fv) * cold + sigm(iv) * tanhf(gv);
            float hn = sigm(ov) * tanhf(cn);
            c[idx] = cn;
            hout[idx] = f2tf32(hn);              // recurrence path: tf32 bits
            if (mode == 1 && t == TT - 1) out[idx] = hn;  // final output: fp32
        }

        gsync();
    }
}

__global__ void copy_kernel(const float* __restrict__ src, float* __restrict__ dst, int n) {
    int i = blockIdx.x * 256 + threadIdx.x;
    if (i < n) dst[i] = src[i];
}

__global__ void cvt_tf32_kernel(const float* __restrict__ src, uint32_t* __restrict__ dst, int n) {
    int i = blockIdx.x * 256 + threadIdx.x;
    if (i < n) dst[i] = f2tf32(src[i]);
}

// ============================================================================
extern "C" void kernel_launch(void* const* d_in, const int* in_sizes, int n_in,
                              void* d_out, int out_size) {
    const float* x    = (const float*)d_in[0];  // [T, N, D]
    const float* h0   = (const float*)d_in[1];  // [L, N, H]
    const float* c0   = (const float*)d_in[2];  // [L, N, H]
    const float* Wih  = (const float*)d_in[3];  // [L, 4H, D]
    const float* Whh  = (const float*)d_in[4];  // [L, 4H, H]
    const float* bih  = (const float*)d_in[5];  // [L, 4H]
    const float* bhh  = (const float*)d_in[6];  // [L, 4H]
    float* out = (float*)d_out;                 // [N, H]

    float *pGx, *pH1, *phA, *phB, *pc, *ph0c;
    cudaGetSymbolAddress((void**)&pGx,  g_Gx);
    cudaGetSymbolAddress((void**)&pH1,  g_H1);
    cudaGetSymbolAddress((void**)&phA,  g_hA);
    cudaGetSymbolAddress((void**)&phB,  g_hB);
    cudaGetSymbolAddress((void**)&pc,   g_c);
    cudaGetSymbolAddress((void**)&ph0c, g_h0c);

    const int SMEM_DYN = (32 * WS_STRIDE + 2 * 128 * HS_STRIDE) * 4;  // 201216 B
    static bool attr_set = false;
    if (!attr_set) {
        cudaFuncSetAttribute(lstm_seq_kernel,
                             cudaFuncAttributeMaxDynamicSharedMemorySize, SMEM_DYN);
        attr_set = true;
    }

    const int M = TT * NB;  // 32768

    // pre-convert h0 (both layers) to tf32 bits
    cvt_tf32_kernel<<<(2 * NH) / 256, 256>>>(h0, (uint32_t*)ph0c, 2 * NH);

    for (int layer = 0; layer < 2; layer++) {
        const float* inp = (layer == 0) ? x : pH1;
        const float* Wl  = Wih + (size_t)layer * G4 * DD;
        const float* Rl  = Whh + (size_t)layer * G4 * HH;

        dim3 grid_g(G4 / 128, M / 128);
        gemm_gx_kernel<<<grid_g, 256>>>(inp, Wl,
                                        bih + (size_t)layer * G4,
                                        bhh + (size_t)layer * G4, pGx);

        copy_kernel<<<NH / 256, 256>>>(c0 + (size_t)layer * NH, pc, NH);

        lstm_seq_kernel<<<NCTAS, 256, SMEM_DYN>>>(
            pGx, Rl, ph0c + (size_t)layer * NH,
            pH1, phA, phB, pc, out, layer);
    }
}

// round 3
// speedup vs baseline: 1.3995x; 1.0845x over previous
#include <cuda_runtime.h>
#include <cstdint>
#include <math.h>

// Problem constants
#define TT 256
#define NB 128
#define DD 1024
#define HH 1024
#define G4 4096                 // 4*H
#define NH (NB * HH)            // 131072

#define NCTAS 128               // persistent grid size (1 CTA/SM)
#define WS_STRIDE 1028          // W smem row stride (words)
#define HS_STRIDE 68            // h smem row stride (words)

#define GS 3                    // gemm pipeline stages
#define GEMM_SMEM (GS * 128 * 36 * 2 * 4)   // 110592 B

// ---------------- scratch (static device memory; no allocation) ----------------
__device__ float    g_Gx[(size_t)TT * NB * G4];   // [T*N, 4H] input projection + bias
__device__ float    g_H1[(size_t)TT * NB * HH];   // layer-0 hidden outputs (tf32 bits)
__device__ uint32_t g_xc[(size_t)TT * NB * DD];   // x pre-converted to tf32 bits
__device__ uint32_t g_Wihc[(size_t)2 * G4 * DD];  // W_ih pre-converted to tf32 bits
__device__ float    g_hA[NH];
__device__ float    g_hB[NH];
__device__ float    g_c[NH];
__device__ float    g_h0c[2 * NH];                // h0 pre-converted to tf32 bits

// grid barrier state
__device__ unsigned g_bar_cnt = 0;
__device__ volatile unsigned g_bar_gen = 0;

// ---------------- helpers ----------------
__device__ __forceinline__ uint32_t f2tf32(float x) {
    uint32_t r;
    asm("cvt.rna.tf32.f32 %0, %1;" : "=r"(r) : "f"(x));
    return r;
}

__device__ __forceinline__ void mma_tf32(float* d,
                                         uint32_t a0, uint32_t a1, uint32_t a2, uint32_t a3,
                                         uint32_t b0, uint32_t b1) {
    asm volatile(
        "mma.sync.aligned.m16n8k8.row.col.f32.tf32.tf32.f32 "
        "{%0,%1,%2,%3}, {%4,%5,%6,%7}, {%8,%9}, {%0,%1,%2,%3};\n"
        : "+f"(d[0]), "+f"(d[1]), "+f"(d[2]), "+f"(d[3])
        : "r"(a0), "r"(a1), "r"(a2), "r"(a3), "r"(b0), "r"(b1));
}

__device__ __forceinline__ float sigm(float x) { return 1.0f / (1.0f + expf(-x)); }

__device__ __forceinline__ void cpasync16(uint32_t* dst_smem, const void* src) {
    uint32_t a = (uint32_t)__cvta_generic_to_shared(dst_smem);
    asm volatile("cp.async.cg.shared.global [%0], [%1], 16;" :: "r"(a), "l"(src));
}
__device__ __forceinline__ void cp_commit() { asm volatile("cp.async.commit_group;"); }
template <int N>
__device__ __forceinline__ void cp_wait() { asm volatile("cp.async.wait_group %0;" :: "n"(N)); }

__device__ __forceinline__ void gsync() {
    __syncthreads();
    if (threadIdx.x == 0) {
        __threadfence();
        unsigned gen = g_bar_gen;
        if (atomicAdd(&g_bar_cnt, 1) == NCTAS - 1) {
            atomicExch(&g_bar_cnt, 0);
            __threadfence();
            g_bar_gen = gen + 1;
        } else {
            while (g_bar_gen == gen) { }
        }
        __threadfence();
    }
    __syncthreads();
}

// ============================================================================
// Pipelined batched input projection:
// out[M,4096] = A[M,1024] @ W[4096,1024]^T + (b_ih+b_hh)
// A and W are PRE-CONVERTED tf32 bits -> raw cp.async, no cvt in hot loop.
// 128x128 tile, K-chunk 32, 3-stage cp.async pipeline, 2 CTAs/SM.
// ============================================================================
__global__ __launch_bounds__(256, 2) void gemm_gx2_kernel(
    const uint32_t* __restrict__ A,     // [M, 1024] tf32 bits
    const uint32_t* __restrict__ W,     // [4096, 1024] tf32 bits
    const float* __restrict__ b_ih,
    const float* __restrict__ b_hh,
    float* __restrict__ out)            // [M, 4096] fp32
{
    extern __shared__ __align__(16) uint32_t gsm[];
    uint32_t* As = gsm;                      // [GS][128][36]
    uint32_t* Ws = gsm + GS * 128 * 36;      // [GS][128][36]

    const int tid  = threadIdx.x;
    const int lane = tid & 31;
    const int warp = tid >> 5;
    const int g    = lane >> 2;
    const int t4   = lane & 3;
    const int wm   = warp & 3;
    const int wn   = warp >> 2;

    const int n0 = blockIdx.x * 128;
    const int m0 = blockIdx.y * 128;

    const int ld_row = tid >> 3;   // 0..31 (x4 iters -> 128 rows)
    const int ld_c4  = tid & 7;

    const uint32_t* Abase = A + (size_t)m0 * 1024 + ld_c4 * 4;
    const uint32_t* Wbase = W + (size_t)n0 * 1024 + ld_c4 * 4;

    auto load_stage = [&](int kt, int s) {
        uint32_t* Ad = As + s * (128 * 36);
        uint32_t* Wd = Ws + s * (128 * 36);
        const uint32_t* Asrc = Abase + kt * 32;
        const uint32_t* Wsrc = Wbase + kt * 32;
#pragma unroll
        for (int i = 0; i < 4; i++) {
            int row = ld_row + i * 32;
            cpasync16(&Ad[row * 36 + ld_c4 * 4], Asrc + (size_t)row * 1024);
            cpasync16(&Wd[row * 36 + ld_c4 * 4], Wsrc + (size_t)row * 1024);
        }
        cp_commit();
    };

    float acc[2][8][4];
#pragma unroll
    for (int mi = 0; mi < 2; mi++)
#pragma unroll
        for (int ni = 0; ni < 8; ni++)
#pragma unroll
            for (int p = 0; p < 4; p++) acc[mi][ni][p] = 0.0f;

    // prologue: stages 0..GS-2
#pragma unroll
    for (int s = 0; s < GS - 1; s++) load_stage(s, s);

    const int NK = 32;  // 1024 / 32
    for (int kt = 0; kt < NK; kt++) {
        if (kt + GS - 1 < NK) {
            load_stage(kt + GS - 1, (kt + GS - 1) % GS);
            cp_wait<GS - 1>();
        } else if (kt < NK - 1) {
            cp_wait<1>();
        } else {
            cp_wait<0>();
        }
        __syncthreads();

        const uint32_t* Ap = As + (kt % GS) * (128 * 36);
        const uint32_t* Wp = Ws + (kt % GS) * (128 * 36);

#pragma unroll
        for (int kk = 0; kk < 32; kk += 8) {
            uint32_t a[2][4];
#pragma unroll
            for (int mi = 0; mi < 2; mi++) {
                int r = wm * 32 + mi * 16;
                a[mi][0] = Ap[(r + g) * 36 + kk + t4];
                a[mi][1] = Ap[(r + g + 8) * 36 + kk + t4];
                a[mi][2] = Ap[(r + g) * 36 + kk + t4 + 4];
                a[mi][3] = Ap[(r + g + 8) * 36 + kk + t4 + 4];
            }
#pragma unroll
            for (int ni = 0; ni < 8; ni++) {
                int wr = wn * 64 + ni * 8 + g;
                uint32_t b0 = Wp[wr * 36 + kk + t4];
                uint32_t b1 = Wp[wr * 36 + kk + t4 + 4];
#pragma unroll
                for (int mi = 0; mi < 2; mi++)
                    mma_tf32(acc[mi][ni], a[mi][0], a[mi][1], a[mi][2], a[mi][3], b0, b1);
            }
        }
        __syncthreads();
    }

    // epilogue: add combined bias, write fp32
#pragma unroll
    for (int mi = 0; mi < 2; mi++) {
#pragma unroll
        for (int ni = 0; ni < 8; ni++) {
            int row = m0 + wm * 32 + mi * 16 + g;
            int col = n0 + wn * 64 + ni * 8 + t4 * 2;
            float bias0 = b_ih[col] + b_hh[col];
            float bias1 = b_ih[col + 1] + b_hh[col + 1];
            out[(size_t)row * 4096 + col]           = acc[mi][ni][0] + bias0;
            out[(size_t)row * 4096 + col + 1]       = acc[mi][ni][1] + bias1;
            out[(size_t)(row + 8) * 4096 + col]     = acc[mi][ni][2] + bias0;
            out[(size_t)(row + 8) * 4096 + col + 1] = acc[mi][ni][3] + bias1;
        }
    }
}

// ============================================================================
// Persistent recurrence kernel (unchanged from round 2).
// ============================================================================
__global__ __launch_bounds__(256) void lstm_seq_kernel(
    const float* __restrict__ Gx_base,
    const float* __restrict__ Whh,
    const float* __restrict__ h0c,
    float* __restrict__ H1,
    float* __restrict__ hA, float* __restrict__ hB,
    float* __restrict__ c,
    float* __restrict__ out,
    int mode)
{
    extern __shared__ __align__(16) uint32_t sm[];
    uint32_t* ws = sm;
    uint32_t* hs[2];
    hs[0] = sm + 32 * WS_STRIDE;
    hs[1] = hs[0] + 128 * HS_STRIDE;

    const int tid  = threadIdx.x;
    const int lane = tid & 31;
    const int warp = tid >> 5;
    const int g    = lane >> 2;
    const int t4   = lane & 3;
    const int hu0  = blockIdx.x * 8;

#pragma unroll
    for (int i = 0; i < 32; i++) {
        int idx4 = tid + i * 256;
        int row  = idx4 >> 8;
        int c4   = idx4 & 255;
        int grow = (row >> 3) * 1024 + hu0 + (row & 7);
        float4 v = *(const float4*)(Whh + (size_t)grow * 1024 + c4 * 4);
        uint4 u; u.x = f2tf32(v.x); u.y = f2tf32(v.y); u.z = f2tf32(v.z); u.w = f2tf32(v.w);
        *(uint4*)&ws[(size_t)row * WS_STRIDE + c4 * 4] = u;
    }
    __syncthreads();

    const int ld_row = tid >> 4;
    const int ld_c4  = tid & 15;

    for (int t = 0; t < TT; t++) {
        const uint32_t* hin;
        if (mode == 0)
            hin = (const uint32_t*)(t == 0 ? h0c : H1 + (size_t)(t - 1) * NH);
        else
            hin = (const uint32_t*)(t == 0 ? h0c : ((t & 1) ? hA : hB));

#pragma unroll
        for (int i = 0; i < 8; i++) {
            int row = ld_row + i * 16;
            cpasync16(&hs[0][(size_t)row * HS_STRIDE + ld_c4 * 4],
                      hin + (size_t)row * 1024 + ld_c4 * 4);
        }
        cp_commit();

        float acc[4][4];
#pragma unroll
        for (int q = 0; q < 4; q++)
#pragma unroll
            for (int p = 0; p < 4; p++) acc[q][p] = 0.0f;

        const int m0 = warp * 16;

        for (int kt = 0; kt < 16; kt++) {
            if (kt < 15) {
                uint32_t* dst = hs[(kt + 1) & 1];
                const uint32_t* src = hin + (size_t)(kt + 1) * 64;
#pragma unroll
                for (int i = 0; i < 8; i++) {
                    int row = ld_row + i * 16;
                    cpasync16(&dst[(size_t)row * HS_STRIDE + ld_c4 * 4],
                              src + (size_t)row * 1024 + ld_c4 * 4);
                }
                cp_commit();
                cp_wait<1>();
            } else {
                cp_wait<0>();
            }
            __syncthreads();

            const uint32_t* hp = hs[kt & 1];
            const int kw = kt * 64;
#pragma unroll
            for (int kk = 0; kk < 64; kk += 8) {
                uint32_t a0 = hp[(size_t)(m0 + g) * HS_STRIDE + kk + t4];
                uint32_t a1 = hp[(size_t)(m0 + g + 8) * HS_STRIDE + kk + t4];
                uint32_t a2 = hp[(size_t)(m0 + g) * HS_STRIDE + kk + t4 + 4];
                uint32_t a3 = hp[(size_t)(m0 + g + 8) * HS_STRIDE + kk + t4 + 4];
#pragma unroll
                for (int q = 0; q < 4; q++) {
                    uint32_t b0 = ws[(size_t)(q * 8 + g) * WS_STRIDE + kw + kk + t4];
                    uint32_t b1 = ws[(size_t)(q * 8 + g) * WS_STRIDE + kw + kk + t4 + 4];
                    mma_tf32(acc[q], a0, a1, a2, a3, b0, b1);
                }
            }
            __syncthreads();
        }

        const float* Gx = Gx_base + (size_t)t * NB * G4;
        uint32_t* hout = (uint32_t*)(mode == 0 ? (H1 + (size_t)t * NH)
                                               : ((t & 1) ? hB : hA));
        const int r0   = warp * 16 + g;
        const int col0 = hu0 + t4 * 2;
#pragma unroll
        for (int q = 0; q < 4; q++) {
            int gc = q * 1024 + col0;
            acc[q][0] += Gx[(size_t)r0 * 4096 + gc];
            acc[q][1] += Gx[(size_t)r0 * 4096 + gc + 1];
            acc[q][2] += Gx[(size_t)(r0 + 8) * 4096 + gc];
            acc[q][3] += Gx[(size_t)(r0 + 8) * 4096 + gc + 1];
        }
#pragma unroll
        for (int p = 0; p < 4; p++) {
            int row = r0 + ((p >= 2) ? 8 : 0);
            int col = col0 + (p & 1);
            size_t idx = (size_t)row * 1024 + col;
            float iv = acc[0][p], fv = acc[1][p], gv = acc[2][p], ov = acc[3][p];
            float cold = c[idx];
            float cn = sigm(fv) * cold + sigm(iv) * tanhf(gv);
            float hn = sigm(ov) * tanhf(cn);
            c[idx] = cn;
            hout[idx] = f2tf32(hn);
            if (mode == 1 && t == TT - 1) out[idx] = hn;
        }

        gsync();
    }
}

__global__ void copy_kernel(const float* __restrict__ src, float* __restrict__ dst, int n) {
    int i = blockIdx.x * 256 + threadIdx.x;
    if (i < n) dst[i] = src[i];
}

__global__ void cvt_tf32_kernel(const float* __restrict__ src, uint32_t* __restrict__ dst, int n) {
    int i = blockIdx.x * 256 + threadIdx.x;
    if (i < n) dst[i] = f2tf32(src[i]);
}

// ============================================================================
extern "C" void kernel_launch(void* const* d_in, const int* in_sizes, int n_in,
                              void* d_out, int out_size) {
    const float* x    = (const float*)d_in[0];
    const float* h0   = (const float*)d_in[1];
    const float* c0   = (const float*)d_in[2];
    const float* Wih  = (const float*)d_in[3];
    const float* Whh  = (const float*)d_in[4];
    const float* bih  = (const float*)d_in[5];
    const float* bhh  = (const float*)d_in[6];
    float* out = (float*)d_out;

    float *pGx, *pH1, *phA, *phB, *pc, *ph0c;
    uint32_t *pxc, *pWihc;
    cudaGetSymbolAddress((void**)&pGx,   g_Gx);
    cudaGetSymbolAddress((void**)&pH1,   g_H1);
    cudaGetSymbolAddress((void**)&phA,   g_hA);
    cudaGetSymbolAddress((void**)&phB,   g_hB);
    cudaGetSymbolAddress((void**)&pc,    g_c);
    cudaGetSymbolAddress((void**)&ph0c,  g_h0c);
    cudaGetSymbolAddress((void**)&pxc,   g_xc);
    cudaGetSymbolAddress((void**)&pWihc, g_Wihc);

    const int SMEM_SEQ = (32 * WS_STRIDE + 2 * 128 * HS_STRIDE) * 4;
    static bool attr_set = false;
    if (!attr_set) {
        cudaFuncSetAttribute(lstm_seq_kernel,
                             cudaFuncAttributeMaxDynamicSharedMemorySize, SMEM_SEQ);
        cudaFuncSetAttribute(gemm_gx2_kernel,
                             cudaFuncAttributeMaxDynamicSharedMemorySize, GEMM_SMEM);
        attr_set = true;
    }

    const int M = TT * NB;  // 32768

    // one-time conversions: h0, x, W_ih -> tf32 bits
    cvt_tf32_kernel<<<(2 * NH) / 256, 256>>>(h0, (uint32_t*)ph0c, 2 * NH);
    cvt_tf32_kernel<<<(TT * NB * DD) / 256, 256>>>(x, pxc, TT * NB * DD);
    cvt_tf32_kernel<<<(2 * G4 * DD) / 256, 256>>>(Wih, pWihc, 2 * G4 * DD);

    for (int layer = 0; layer < 2; layer++) {
        const uint32_t* inp = (layer == 0) ? pxc : (const uint32_t*)pH1;
        const uint32_t* Wl  = pWihc + (size_t)layer * G4 * DD;
        const float*    Rl  = Whh + (size_t)layer * G4 * HH;

        dim3 grid_g(G4 / 128, M / 128);
        gemm_gx2_kernel<<<grid_g, 256, GEMM_SMEM>>>(
            inp, Wl, bih + (size_t)layer * G4, bhh + (size_t)layer * G4, pGx);

        copy_kernel<<<NH / 256, 256>>>(c0 + (size_t)layer * NH, pc, NH);

        lstm_seq_kernel<<<NCTAS, 256, SMEM_SEQ>>>(
            pGx, Rl, ph0c + (size_t)layer * NH,
            pH1, phA, phB, pc, out, layer);
    }
}

// round 4
// speedup vs baseline: 1.4404x; 1.0292x over previous
#include <cuda_runtime.h>
#include <cstdint>
#include <math.h>

// Problem constants
#define TT 256
#define NB 128
#define DD 1024
#define HH 1024
#define G4 4096                 // 4*H
#define NH (NB * HH)            // 131072

#define NCTAS 128               // persistent grid size (1 CTA/SM)
#define WS_STRIDE 1028          // W smem row stride (words)

#define HSTAGES 5               // recurrence h pipeline stages (32-col tiles)
#define HTILE_W 36              // words per row in h stage (32 + pad)
#define SMEM_SEQ ((32 * WS_STRIDE + HSTAGES * 128 * HTILE_W) * 4)  // 223744 B

#define GS 3                    // gemm pipeline stages
#define GEMM_SMEM (GS * 128 * 36 * 2 * 4)   // 110592 B

// ---------------- scratch (static device memory; no allocation) ----------------
__device__ float    g_Gx[(size_t)TT * NB * G4];   // [T*N, 4H] input projection + bias
__device__ float    g_H1[(size_t)TT * NB * HH];   // layer-0 hidden outputs (tf32 bits)
__device__ uint32_t g_xc[(size_t)TT * NB * DD];   // x pre-converted to tf32 bits
__device__ uint32_t g_Wihc[(size_t)2 * G4 * DD];  // W_ih pre-converted to tf32 bits
__device__ float    g_hA[NH];
__device__ float    g_hB[NH];
__device__ float    g_h0c[2 * NH];                // h0 pre-converted to tf32 bits

// grid barrier state
__device__ unsigned g_bar_cnt = 0;
__device__ volatile unsigned g_bar_gen = 0;

// ---------------- helpers ----------------
__device__ __forceinline__ uint32_t f2tf32(float x) {
    uint32_t r;
    asm("cvt.rna.tf32.f32 %0, %1;" : "=r"(r) : "f"(x));
    return r;
}

__device__ __forceinline__ void mma_tf32(float* d,
                                         uint32_t a0, uint32_t a1, uint32_t a2, uint32_t a3,
                                         uint32_t b0, uint32_t b1) {
    asm volatile(
        "mma.sync.aligned.m16n8k8.row.col.f32.tf32.tf32.f32 "
        "{%0,%1,%2,%3}, {%4,%5,%6,%7}, {%8,%9}, {%0,%1,%2,%3};\n"
        : "+f"(d[0]), "+f"(d[1]), "+f"(d[2]), "+f"(d[3])
        : "r"(a0), "r"(a1), "r"(a2), "r"(a3), "r"(b0), "r"(b1));
}

__device__ __forceinline__ float sigm(float x) { return 1.0f / (1.0f + expf(-x)); }

__device__ __forceinline__ void cpasync16(uint32_t* dst_smem, const void* src) {
    uint32_t a = (uint32_t)__cvta_generic_to_shared(dst_smem);
    asm volatile("cp.async.cg.shared.global [%0], [%1], 16;" :: "r"(a), "l"(src));
}
__device__ __forceinline__ void cp_commit() { asm volatile("cp.async.commit_group;"); }
template <int N>
__device__ __forceinline__ void cp_wait() { asm volatile("cp.async.wait_group %0;" :: "n"(N)); }

__device__ __forceinline__ void gsync() {
    __syncthreads();
    if (threadIdx.x == 0) {
        __threadfence();
        unsigned gen = g_bar_gen;
        if (atomicAdd(&g_bar_cnt, 1) == NCTAS - 1) {
            atomicExch(&g_bar_cnt, 0);
            __threadfence();
            g_bar_gen = gen + 1;
        } else {
            while (g_bar_gen == gen) { }
        }
        __threadfence();
    }
    __syncthreads();
}

// ============================================================================
// Pipelined batched input projection (unchanged from round 3):
// out[M,4096] = A[M,1024] @ W[4096,1024]^T + (b_ih+b_hh)
// ============================================================================
__global__ __launch_bounds__(256, 2) void gemm_gx2_kernel(
    const uint32_t* __restrict__ A,
    const uint32_t* __restrict__ W,
    const float* __restrict__ b_ih,
    const float* __restrict__ b_hh,
    float* __restrict__ out)
{
    extern __shared__ __align__(16) uint32_t gsm[];
    uint32_t* As = gsm;
    uint32_t* Ws = gsm + GS * 128 * 36;

    const int tid  = threadIdx.x;
    const int lane = tid & 31;
    const int warp = tid >> 5;
    const int g    = lane >> 2;
    const int t4   = lane & 3;
    const int wm   = warp & 3;
    const int wn   = warp >> 2;

    const int n0 = blockIdx.x * 128;
    const int m0 = blockIdx.y * 128;

    const int ld_row = tid >> 3;
    const int ld_c4  = tid & 7;

    const uint32_t* Abase = A + (size_t)m0 * 1024 + ld_c4 * 4;
    const uint32_t* Wbase = W + (size_t)n0 * 1024 + ld_c4 * 4;

    auto load_stage = [&](int kt, int s) {
        uint32_t* Ad = As + s * (128 * 36);
        uint32_t* Wd = Ws + s * (128 * 36);
        const uint32_t* Asrc = Abase + kt * 32;
        const uint32_t* Wsrc = Wbase + kt * 32;
#pragma unroll
        for (int i = 0; i < 4; i++) {
            int row = ld_row + i * 32;
            cpasync16(&Ad[row * 36 + ld_c4 * 4], Asrc + (size_t)row * 1024);
            cpasync16(&Wd[row * 36 + ld_c4 * 4], Wsrc + (size_t)row * 1024);
        }
        cp_commit();
    };

    float acc[2][8][4];
#pragma unroll
    for (int mi = 0; mi < 2; mi++)
#pragma unroll
        for (int ni = 0; ni < 8; ni++)
#pragma unroll
            for (int p = 0; p < 4; p++) acc[mi][ni][p] = 0.0f;

#pragma unroll
    for (int s = 0; s < GS - 1; s++) load_stage(s, s);

    const int NK = 32;
    for (int kt = 0; kt < NK; kt++) {
        if (kt + GS - 1 < NK) {
            load_stage(kt + GS - 1, (kt + GS - 1) % GS);
            cp_wait<GS - 1>();
        } else if (kt < NK - 1) {
            cp_wait<1>();
        } else {
            cp_wait<0>();
        }
        __syncthreads();

        const uint32_t* Ap = As + (kt % GS) * (128 * 36);
        const uint32_t* Wp = Ws + (kt % GS) * (128 * 36);

#pragma unroll
        for (int kk = 0; kk < 32; kk += 8) {
            uint32_t a[2][4];
#pragma unroll
            for (int mi = 0; mi < 2; mi++) {
                int r = wm * 32 + mi * 16;
                a[mi][0] = Ap[(r + g) * 36 + kk + t4];
                a[mi][1] = Ap[(r + g + 8) * 36 + kk + t4];
                a[mi][2] = Ap[(r + g) * 36 + kk + t4 + 4];
                a[mi][3] = Ap[(r + g + 8) * 36 + kk + t4 + 4];
            }
#pragma unroll
            for (int ni = 0; ni < 8; ni++) {
                int wr = wn * 64 + ni * 8 + g;
                uint32_t b0 = Wp[wr * 36 + kk + t4];
                uint32_t b1 = Wp[wr * 36 + kk + t4 + 4];
#pragma unroll
                for (int mi = 0; mi < 2; mi++)
                    mma_tf32(acc[mi][ni], a[mi][0], a[mi][1], a[mi][2], a[mi][3], b0, b1);
            }
        }
        __syncthreads();
    }

#pragma unroll
    for (int mi = 0; mi < 2; mi++) {
#pragma unroll
        for (int ni = 0; ni < 8; ni++) {
            int row = m0 + wm * 32 + mi * 16 + g;
            int col = n0 + wn * 64 + ni * 8 + t4 * 2;
            float bias0 = b_ih[col] + b_hh[col];
            float bias1 = b_ih[col + 1] + b_hh[col + 1];
            out[(size_t)row * 4096 + col]           = acc[mi][ni][0] + bias0;
            out[(size_t)row * 4096 + col + 1]       = acc[mi][ni][1] + bias1;
            out[(size_t)(row + 8) * 4096 + col]     = acc[mi][ni][2] + bias0;
            out[(size_t)(row + 8) * 4096 + col + 1] = acc[mi][ni][3] + bias1;
        }
    }
}

// ============================================================================
// Persistent recurrence kernel, round-4 version:
//  - 32-col k-tiles, 5-stage cp.async pipeline, ONE __syncthreads per tile
//  - Gx prefetched to registers at step start
//  - c held in registers for the whole layer (thread-private mapping)
// ============================================================================
__global__ __launch_bounds__(256) void lstm_seq_kernel(
    const float* __restrict__ Gx_base,   // [T, 128, 4096]
    const float* __restrict__ Whh,       // [4096, 1024] fp32 (this layer)
    const float* __restrict__ h0c,       // [128,1024] tf32 bits
    const float* __restrict__ c0l,       // [128,1024] fp32 (this layer)
    float* __restrict__ H1,              // mode0: output sequence (tf32 bits)
    float* __restrict__ hA, float* __restrict__ hB,  // mode1 ping-pong
    float* __restrict__ out,             // mode1: final fp32 [128,1024]
    int mode)
{
    extern __shared__ __align__(16) uint32_t sm[];
    uint32_t* ws = sm;                            // [32][WS_STRIDE]
    uint32_t* hs = sm + 32 * WS_STRIDE;           // [HSTAGES][128][HTILE_W]

    const int tid  = threadIdx.x;
    const int lane = tid & 31;
    const int warp = tid >> 5;
    const int g    = lane >> 2;
    const int t4   = lane & 3;
    const int hu0  = blockIdx.x * 8;

    // ---- load W slab once: 32 gate rows x 1024, cvt to tf32 ----
#pragma unroll
    for (int i = 0; i < 32; i++) {
        int idx4 = tid + i * 256;
        int row  = idx4 >> 8;
        int c4   = idx4 & 255;
        int grow = (row >> 3) * 1024 + hu0 + (row & 7);
        float4 v = *(const float4*)(Whh + (size_t)grow * 1024 + c4 * 4);
        uint4 u; u.x = f2tf32(v.x); u.y = f2tf32(v.y); u.z = f2tf32(v.z); u.w = f2tf32(v.w);
        *(uint4*)&ws[(size_t)row * WS_STRIDE + c4 * 4] = u;
    }
    __syncthreads();

    const int ld_row = tid >> 3;   // 0..31 (x4 iters -> 128 rows)
    const int ld_c4  = tid & 7;
    const int m0     = warp * 16;
    const int r0     = warp * 16 + g;
    const int col0   = hu0 + t4 * 2;

    // ---- c in registers for the whole layer ----
    float creg[4];
#pragma unroll
    for (int p = 0; p < 4; p++) {
        int row = r0 + ((p >= 2) ? 8 : 0);
        int col = col0 + (p & 1);
        creg[p] = c0l[(size_t)row * 1024 + col];
    }

    for (int t = 0; t < TT; t++) {
        const uint32_t* hin;
        if (mode == 0)
            hin = (const uint32_t*)(t == 0 ? h0c : H1 + (size_t)(t - 1) * NH);
        else
            hin = (const uint32_t*)(t == 0 ? h0c : ((t & 1) ? hA : hB));

        // ---- Gx prefetch to registers (overlaps entire k-loop) ----
        const float* Gx = Gx_base + (size_t)t * NB * G4;
        float2 gx[4][2];
#pragma unroll
        for (int q = 0; q < 4; q++) {
            gx[q][0] = __ldg((const float2*)(Gx + (size_t)r0 * 4096 + q * 1024 + col0));
            gx[q][1] = __ldg((const float2*)(Gx + (size_t)(r0 + 8) * 4096 + q * 1024 + col0));
        }

        auto load_tile = [&](int kt) {
            uint32_t* dst = hs + (kt % HSTAGES) * (128 * HTILE_W);
            const uint32_t* src = hin + (size_t)kt * 32 + ld_c4 * 4;
#pragma unroll
            for (int i = 0; i < 4; i++) {
                int row = ld_row + i * 32;
                cpasync16(&dst[row * HTILE_W + ld_c4 * 4], src + (size_t)row * 1024);
            }
            cp_commit();
        };

        float acc[4][4];
#pragma unroll
        for (int q = 0; q < 4; q++)
#pragma unroll
            for (int p = 0; p < 4; p++) acc[q][p] = 0.0f;

        auto compute_tile = [&](int kt) {
            const uint32_t* hp = hs + (kt % HSTAGES) * (128 * HTILE_W);
            const int kw = kt * 32;
#pragma unroll
            for (int kk = 0; kk < 32; kk += 8) {
                uint32_t a0 = hp[(m0 + g) * HTILE_W + kk + t4];
                uint32_t a1 = hp[(m0 + g + 8) * HTILE_W + kk + t4];
                uint32_t a2 = hp[(m0 + g) * HTILE_W + kk + t4 + 4];
                uint32_t a3 = hp[(m0 + g + 8) * HTILE_W + kk + t4 + 4];
#pragma unroll
                for (int q = 0; q < 4; q++) {
                    uint32_t b0 = ws[(size_t)(q * 8 + g) * WS_STRIDE + kw + kk + t4];
                    uint32_t b1 = ws[(size_t)(q * 8 + g) * WS_STRIDE + kw + kk + t4 + 4];
                    mma_tf32(acc[q], a0, a1, a2, a3, b0, b1);
                }
            }
        };

        // prologue: tiles 0..3 in flight
#pragma unroll
        for (int s = 0; s < HSTAGES - 1; s++) load_tile(s);

        // main: wait(kt) -> sync -> issue(kt+4) -> compute(kt)
        for (int kt = 0; kt <= 28; kt++) {
            cp_wait<3>();
            __syncthreads();
            if (kt + 4 < 32) load_tile(kt + 4);
            compute_tile(kt);
        }
        // tail
        cp_wait<2>(); __syncthreads(); compute_tile(29);
        cp_wait<1>(); __syncthreads(); compute_tile(30);
        cp_wait<0>(); __syncthreads(); compute_tile(31);

        // ---- epilogue: add Gx (registers), pointwise -> c (regs), h ----
        uint32_t* hout = (uint32_t*)(mode == 0 ? (H1 + (size_t)t * NH)
                                               : ((t & 1) ? hB : hA));
#pragma unroll
        for (int q = 0; q < 4; q++) {
            acc[q][0] += gx[q][0].x;
            acc[q][1] += gx[q][0].y;
            acc[q][2] += gx[q][1].x;
            acc[q][3] += gx[q][1].y;
        }
#pragma unroll
        for (int p = 0; p < 4; p++) {
            int row = r0 + ((p >= 2) ? 8 : 0);
            int col = col0 + (p & 1);
            size_t idx = (size_t)row * 1024 + col;
            float iv = acc[0][p], fv = acc[1][p], gv = acc[2][p], ov = acc[3][p];
            float cn = sigm(fv) * creg[p] + sigm(iv) * tanhf(gv);
            float hn = sigm(ov) * tanhf(cn);
            creg[p] = cn;
            hout[idx] = f2tf32(hn);
            if (mode == 1 && t == TT - 1) out[idx] = hn;
        }

        gsync();
    }
}

__global__ void cvt_tf32_kernel(const float* __restrict__ src, uint32_t* __restrict__ dst, int n) {
    int i = blockIdx.x * 256 + threadIdx.x;
    if (i < n) dst[i] = f2tf32(src[i]);
}

// ============================================================================
extern "C" void kernel_launch(void* const* d_in, const int* in_sizes, int n_in,
                              void* d_out, int out_size) {
    const float* x    = (const float*)d_in[0];
    const float* h0   = (const float*)d_in[1];
    const float* c0   = (const float*)d_in[2];
    const float* Wih  = (const float*)d_in[3];
    const float* Whh  = (const float*)d_in[4];
    const float* bih  = (const float*)d_in[5];
    const float* bhh  = (const float*)d_in[6];
    float* out = (float*)d_out;

    float *pGx, *pH1, *phA, *phB, *ph0c;
    uint32_t *pxc, *pWihc;
    cudaGetSymbolAddress((void**)&pGx,   g_Gx);
    cudaGetSymbolAddress((void**)&pH1,   g_H1);
    cudaGetSymbolAddress((void**)&phA,   g_hA);
    cudaGetSymbolAddress((void**)&phB,   g_hB);
    cudaGetSymbolAddress((void**)&ph0c,  g_h0c);
    cudaGetSymbolAddress((void**)&pxc,   g_xc);
    cudaGetSymbolAddress((void**)&pWihc, g_Wihc);

    static bool attr_set = false;
    if (!attr_set) {
        cudaFuncSetAttribute(lstm_seq_kernel,
                             cudaFuncAttributeMaxDynamicSharedMemorySize, SMEM_SEQ);
        cudaFuncSetAttribute(gemm_gx2_kernel,
                             cudaFuncAttributeMaxDynamicSharedMemorySize, GEMM_SMEM);
        attr_set = true;
    }

    const int M = TT * NB;  // 32768

    // one-time conversions: h0, x, W_ih -> tf32 bits
    cvt_tf32_kernel<<<(2 * NH) / 256, 256>>>(h0, (uint32_t*)ph0c, 2 * NH);
    cvt_tf32_kernel<<<(TT * NB * DD) / 256, 256>>>(x, pxc, TT * NB * DD);
    cvt_tf32_kernel<<<(2 * G4 * DD) / 256, 256>>>(Wih, pWihc, 2 * G4 * DD);

    for (int layer = 0; layer < 2; layer++) {
        const uint32_t* inp = (layer == 0) ? pxc : (const uint32_t*)pH1;
        const uint32_t* Wl  = pWihc + (size_t)layer * G4 * DD;
        const float*    Rl  = Whh + (size_t)layer * G4 * HH;

        dim3 grid_g(G4 / 128, M / 128);
        gemm_gx2_kernel<<<grid_g, 256, GEMM_SMEM>>>(
            inp, Wl, bih + (size_t)layer * G4, bhh + (size_t)layer * G4, pGx);

        lstm_seq_kernel<<<NCTAS, 256, SMEM_SEQ>>>(
            pGx, Rl, ph0c + (size_t)layer * NH, c0 + (size_t)layer * NH,
            pH1, phA, phB, out, layer);
    }
}

// round 6
// speedup vs baseline: 1.5829x; 1.0989x over previous
#include <cuda_runtime.h>
#include <cstdint>
#include <math.h>

// Problem constants
#define TT 256
#define NB 128
#define DD 1024
#define HH 1024
#define G4 4096                 // 4*H
#define NH (NB * HH)            // 131072

#define NCTAS 128               // persistent grid size (1 CTA/SM)
#define WS_STRIDE 1028          // W smem row stride (words)

#define HSTAGES 5               // recurrence h pipeline stages (32-col tiles)
#define HTILE_W 36              // words per row in h stage (32 + pad)
#define SMEM_SEQ ((32 * WS_STRIDE + HSTAGES * 128 * HTILE_W) * 4)  // 223744 B

#define GS 3                    // gemm pipeline stages
#define GEMM_SMEM (GS * 128 * 36 * 2 * 4)   // 110592 B

// ---------------- scratch (static device memory; no allocation) ----------------
__device__ float    g_Gx[(size_t)TT * NB * G4];   // [T*N, 4H] input projection + bias
__device__ float    g_H1[(size_t)TT * NB * HH];   // layer-0 hidden outputs (tf32 bits)
__device__ uint32_t g_xc[(size_t)TT * NB * DD];   // x pre-converted to tf32 bits
__device__ uint32_t g_Wihc[(size_t)2 * G4 * DD];  // W_ih pre-converted to tf32 bits
__device__ float    g_hA[NH];
__device__ float    g_hB[NH];
__device__ float    g_h0c[2 * NH];                // h0 pre-converted to tf32 bits

// grid barrier state
__device__ unsigned g_bar_cnt = 0;
__device__ volatile unsigned g_bar_gen = 0;

// ---------------- helpers ----------------
__device__ __forceinline__ uint32_t f2tf32(float x) {
    uint32_t r;
    asm("cvt.rna.tf32.f32 %0, %1;" : "=r"(r) : "f"(x));
    return r;
}

__device__ __forceinline__ void mma_tf32(float* d,
                                         uint32_t a0, uint32_t a1, uint32_t a2, uint32_t a3,
                                         uint32_t b0, uint32_t b1) {
    asm volatile(
        "mma.sync.aligned.m16n8k8.row.col.f32.tf32.tf32.f32 "
        "{%0,%1,%2,%3}, {%4,%5,%6,%7}, {%8,%9}, {%0,%1,%2,%3};\n"
        : "+f"(d[0]), "+f"(d[1]), "+f"(d[2]), "+f"(d[3])
        : "r"(a0), "r"(a1), "r"(a2), "r"(a3), "r"(b0), "r"(b1));
}

__device__ __forceinline__ float sigm(float x) { return 1.0f / (1.0f + expf(-x)); }

__device__ __forceinline__ void cpasync16(uint32_t* dst_smem, const void* src) {
    uint32_t a = (uint32_t)__cvta_generic_to_shared(dst_smem);
    asm volatile("cp.async.cg.shared.global [%0], [%1], 16;" :: "r"(a), "l"(src));
}
__device__ __forceinline__ void cp_commit() { asm volatile("cp.async.commit_group;"); }
template <int N>
__device__ __forceinline__ void cp_wait() { asm volatile("cp.async.wait_group %0;" :: "n"(N)); }

__device__ __forceinline__ void gsync() {
    __syncthreads();
    if (threadIdx.x == 0) {
        __threadfence();
        unsigned gen = g_bar_gen;
        if (atomicAdd(&g_bar_cnt, 1) == NCTAS - 1) {
            atomicExch(&g_bar_cnt, 0);
            __threadfence();
            g_bar_gen = gen + 1;
        } else {
            while (g_bar_gen == gen) { }
        }
        __threadfence();
    }
    __syncthreads();
}

// ============================================================================
// Pipelined batched input projection (unchanged):
// out[M,4096] = A[M,1024] @ W[4096,1024]^T + (b_ih+b_hh)
// ============================================================================
__global__ __launch_bounds__(256, 2) void gemm_gx2_kernel(
    const uint32_t* __restrict__ A,
    const uint32_t* __restrict__ W,
    const float* __restrict__ b_ih,
    const float* __restrict__ b_hh,
    float* __restrict__ out)
{
    extern __shared__ __align__(16) uint32_t gsm[];
    uint32_t* As = gsm;
    uint32_t* Ws = gsm + GS * 128 * 36;

    const int tid  = threadIdx.x;
    const int lane = tid & 31;
    const int warp = tid >> 5;
    const int g    = lane >> 2;
    const int t4   = lane & 3;
    const int wm   = warp & 3;
    const int wn   = warp >> 2;

    const int n0 = blockIdx.x * 128;
    const int m0 = blockIdx.y * 128;

    const int ld_row = tid >> 3;
    const int ld_c4  = tid & 7;

    const uint32_t* Abase = A + (size_t)m0 * 1024 + ld_c4 * 4;
    const uint32_t* Wbase = W + (size_t)n0 * 1024 + ld_c4 * 4;

    auto load_stage = [&](int kt, int s) {
        uint32_t* Ad = As + s * (128 * 36);
        uint32_t* Wd = Ws + s * (128 * 36);
        const uint32_t* Asrc = Abase + kt * 32;
        const uint32_t* Wsrc = Wbase + kt * 32;
#pragma unroll
        for (int i = 0; i < 4; i++) {
            int row = ld_row + i * 32;
            cpasync16(&Ad[row * 36 + ld_c4 * 4], Asrc + (size_t)row * 1024);
            cpasync16(&Wd[row * 36 + ld_c4 * 4], Wsrc + (size_t)row * 1024);
        }
        cp_commit();
    };

    float acc[2][8][4];
#pragma unroll
    for (int mi = 0; mi < 2; mi++)
#pragma unroll
        for (int ni = 0; ni < 8; ni++)
#pragma unroll
            for (int p = 0; p < 4; p++) acc[mi][ni][p] = 0.0f;

#pragma unroll
    for (int s = 0; s < GS - 1; s++) load_stage(s, s);

    const int NK = 32;
    for (int kt = 0; kt < NK; kt++) {
        if (kt + GS - 1 < NK) {
            load_stage(kt + GS - 1, (kt + GS - 1) % GS);
            cp_wait<GS - 1>();
        } else if (kt < NK - 1) {
            cp_wait<1>();
        } else {
            cp_wait<0>();
        }
        __syncthreads();

        const uint32_t* Ap = As + (kt % GS) * (128 * 36);
        const uint32_t* Wp = Ws + (kt % GS) * (128 * 36);

#pragma unroll
        for (int kk = 0; kk < 32; kk += 8) {
            uint32_t a[2][4];
#pragma unroll
            for (int mi = 0; mi < 2; mi++) {
                int r = wm * 32 + mi * 16;
                a[mi][0] = Ap[(r + g) * 36 + kk + t4];
                a[mi][1] = Ap[(r + g + 8) * 36 + kk + t4];
                a[mi][2] = Ap[(r + g) * 36 + kk + t4 + 4];
                a[mi][3] = Ap[(r + g + 8) * 36 + kk + t4 + 4];
            }
#pragma unroll
            for (int ni = 0; ni < 8; ni++) {
                int wr = wn * 64 + ni * 8 + g;
                uint32_t b0 = Wp[wr * 36 + kk + t4];
                uint32_t b1 = Wp[wr * 36 + kk + t4 + 4];
#pragma unroll
                for (int mi = 0; mi < 2; mi++)
                    mma_tf32(acc[mi][ni], a[mi][0], a[mi][1], a[mi][2], a[mi][3], b0, b1);
            }
        }
        __syncthreads();
    }

#pragma unroll
    for (int mi = 0; mi < 2; mi++) {
#pragma unroll
        for (int ni = 0; ni < 8; ni++) {
            int row = m0 + wm * 32 + mi * 16 + g;
            int col = n0 + wn * 64 + ni * 8 + t4 * 2;
            float bias0 = b_ih[col] + b_hh[col];
            float bias1 = b_ih[col + 1] + b_hh[col + 1];
            out[(size_t)row * 4096 + col]           = acc[mi][ni][0] + bias0;
            out[(size_t)row * 4096 + col + 1]       = acc[mi][ni][1] + bias1;
            out[(size_t)(row + 8) * 4096 + col]     = acc[mi][ni][2] + bias0;
            out[(size_t)(row + 8) * 4096 + col + 1] = acc[mi][ni][3] + bias1;
        }
    }
}

// ============================================================================
// Persistent recurrence kernel, round-6 version:
//  - 8 warps = 4 m-tiles (32 rows) x 2 k-halves (512 cols each)
//  - warp tile m32 x n32: operand smem bytes/MMA = 2 regs (was 3)
//  - k-halves reduced through a 16KB smem exchange per step
//  - epilogue (Gx add, pointwise, c-regs, h store) in the kw=0 warps
// ============================================================================
__global__ __launch_bounds__(256) void lstm_seq_kernel(
    const float* __restrict__ Gx_base,   // [T, 128, 4096]
    const float* __restrict__ Whh,       // [4096, 1024] fp32 (this layer)
    const float* __restrict__ h0c,       // [128,1024] tf32 bits
    const float* __restrict__ c0l,       // [128,1024] fp32 (this layer)
    float* __restrict__ H1,              // mode0: output sequence (tf32 bits)
    float* __restrict__ hA, float* __restrict__ hB,  // mode1 ping-pong
    float* __restrict__ out,             // mode1: final fp32 [128,1024]
    int mode)
{
    extern __shared__ __align__(16) uint32_t sm[];
    uint32_t* ws = sm;                            // [32][WS_STRIDE]
    uint32_t* hs = sm + 32 * WS_STRIDE;           // [HSTAGES][128][HTILE_W]
    float*   red = (float*)hs;                    // reused post-pipeline (16KB)

    const int tid  = threadIdx.x;
    const int lane = tid & 31;
    const int warp = tid >> 5;
    const int g    = lane >> 2;
    const int t4   = lane & 3;
    const int kw   = warp >> 2;   // 0,1: k half
    const int mw   = warp & 3;    // 0..3: 32-row m tile
    const int hu0  = blockIdx.x * 8;

    // ---- load W slab once: 32 gate rows x 1024, cvt to tf32 ----
#pragma unroll
    for (int i = 0; i < 32; i++) {
        int idx4 = tid + i * 256;
        int row  = idx4 >> 8;
        int c4   = idx4 & 255;
        int grow = (row >> 3) * 1024 + hu0 + (row & 7);
        float4 v = *(const float4*)(Whh + (size_t)grow * 1024 + c4 * 4);
        uint4 u; u.x = f2tf32(v.x); u.y = f2tf32(v.y); u.z = f2tf32(v.z); u.w = f2tf32(v.w);
        *(uint4*)&ws[(size_t)row * WS_STRIDE + c4 * 4] = u;
    }
    __syncthreads();

    const int ld_row = tid >> 3;   // 0..31 (x4 iters -> 128 rows)
    const int ld_c4  = tid & 7;

    // ---- c in registers (kw=0 warps): rows mw*32+g + {0,8,16,24}, units t4*2,+1 ----
    float2 creg[4];
    if (kw == 0) {
#pragma unroll
        for (int r4 = 0; r4 < 4; r4++) {
            int row = mw * 32 + g + r4 * 8;
            creg[r4] = __ldg((const float2*)(c0l + (size_t)row * 1024 + hu0 + t4 * 2));
        }
    }

    for (int t = 0; t < TT; t++) {
        const uint32_t* hin;
        if (mode == 0)
            hin = (const uint32_t*)(t == 0 ? h0c : H1 + (size_t)(t - 1) * NH);
        else
            hin = (const uint32_t*)(t == 0 ? h0c : ((t & 1) ? hA : hB));

        // ---- Gx prefetch to registers (kw=0 warps; overlaps entire k-loop) ----
        const float* Gx = Gx_base + (size_t)t * NB * G4;
        float2 gxr[4][4];
        if (kw == 0) {
#pragma unroll
            for (int r4 = 0; r4 < 4; r4++) {
                int row = mw * 32 + g + r4 * 8;
#pragma unroll
                for (int q = 0; q < 4; q++)
                    gxr[r4][q] = __ldg((const float2*)(Gx + (size_t)row * 4096 +
                                                       q * 1024 + hu0 + t4 * 2));
            }
        }

        auto load_tile = [&](int kt) {
            uint32_t* dst = hs + (kt % HSTAGES) * (128 * HTILE_W);
            const uint32_t* src = hin + (size_t)kt * 32 + ld_c4 * 4;
#pragma unroll
            for (int i = 0; i < 4; i++) {
                int row = ld_row + i * 32;
                cpasync16(&dst[row * HTILE_W + ld_c4 * 4], src + (size_t)row * 1024);
            }
            cp_commit();
        };

        float acc[2][4][4];   // [m-frag][gate][c]
#pragma unroll
        for (int mi = 0; mi < 2; mi++)
#pragma unroll
            for (int q = 0; q < 4; q++)
#pragma unroll
                for (int p = 0; p < 4; p++) acc[mi][q][p] = 0.0f;

        auto compute_tile = [&](int kt) {
            if ((kt >> 4) != kw) return;          // k-split ownership
            const uint32_t* hp = hs + (kt % HSTAGES) * (128 * HTILE_W);
            const int kb = kt * 32;
#pragma unroll
            for (int kk = 0; kk < 32; kk += 8) {
                uint32_t a[2][4];
#pragma unroll
                for (int mi = 0; mi < 2; mi++) {
                    int r = mw * 32 + mi * 16;
                    a[mi][0] = hp[(r + g) * HTILE_W + kk + t4];
                    a[mi][1] = hp[(r + g + 8) * HTILE_W + kk + t4];
                    a[mi][2] = hp[(r + g) * HTILE_W + kk + t4 + 4];
                    a[mi][3] = hp[(r + g + 8) * HTILE_W + kk + t4 + 4];
                }
#pragma unroll
                for (int q = 0; q < 4; q++) {
                    uint32_t b0 = ws[(size_t)(q * 8 + g) * WS_STRIDE + kb + kk + t4];
                    uint32_t b1 = ws[(size_t)(q * 8 + g) * WS_STRIDE + kb + kk + t4 + 4];
#pragma unroll
                    for (int mi = 0; mi < 2; mi++)
                        mma_tf32(acc[mi][q], a[mi][0], a[mi][1], a[mi][2], a[mi][3], b0, b1);
                }
            }
        };

        // prologue: tiles 0..3 in flight
#pragma unroll
        for (int s = 0; s < HSTAGES - 1; s++) load_tile(s);

        for (int kt = 0; kt <= 28; kt++) {
            cp_wait<3>();
            __syncthreads();
            if (kt + 4 < 32) load_tile(kt + 4);
            compute_tile(kt);
        }
        cp_wait<2>(); __syncthreads(); compute_tile(29);
        cp_wait<1>(); __syncthreads(); compute_tile(30);
        cp_wait<0>(); __syncthreads(); compute_tile(31);

        // ---- cross-k reduction through smem ----
        __syncthreads();                          // all buffers consumed
        if (kw == 1) {
            float* dst = red + mw * 1024;
#pragma unroll
            for (int mi = 0; mi < 2; mi++)
#pragma unroll
                for (int q = 0; q < 4; q++)
#pragma unroll
                    for (int p = 0; p < 4; p++)
                        dst[((mi * 4 + q) * 4 + p) * 32 + lane] = acc[mi][q][p];
        }
        __syncthreads();

        if (kw == 0) {
            const float* srcr = red + mw * 1024;
#pragma unroll
            for (int mi = 0; mi < 2; mi++)
#pragma unroll
                for (int q = 0; q < 4; q++)
#pragma unroll
                    for (int p = 0; p < 4; p++)
                        acc[mi][q][p] += srcr[((mi * 4 + q) * 4 + p) * 32 + lane];

            // ---- epilogue: Gx (regs) + pointwise -> c (regs), h ----
            uint32_t* hout = (uint32_t*)(mode == 0 ? (H1 + (size_t)t * NH)
                                                   : ((t & 1) ? hB : hA));
#pragma unroll
            for (int mi = 0; mi < 2; mi++) {
#pragma unroll
                for (int ph = 0; ph < 2; ph++) {
                    int r4  = mi * 2 + ph;
                    int row = mw * 32 + g + r4 * 8;
                    float hv[2];
#pragma unroll
                    for (int uu = 0; uu < 2; uu++) {
                        int p = ph * 2 + uu;
                        float iv = acc[mi][0][p] + (uu ? gxr[r4][0].y : gxr[r4][0].x);
                        float fv = acc[mi][1][p] + (uu ? gxr[r4][1].y : gxr[r4][1].x);
                        float gv = acc[mi][2][p] + (uu ? gxr[r4][2].y : gxr[r4][2].x);
                        float ov = acc[mi][3][p] + (uu ? gxr[r4][3].y : gxr[r4][3].x);
                        float cold = uu ? creg[r4].y : creg[r4].x;
                        float cn = sigm(fv) * cold + sigm(iv) * tanhf(gv);
                        float hn = sigm(ov) * tanhf(cn);
                        if (uu) creg[r4].y = cn; else creg[r4].x = cn;
                        hv[uu] = hn;
                    }
                    size_t idx = (size_t)row * 1024 + hu0 + t4 * 2;
                    uint2 hw = make_uint2(f2tf32(hv[0]), f2tf32(hv[1]));
                    *(uint2*)(hout + idx) = hw;
                    if (mode == 1 && t == TT - 1)
                        *(float2*)(out + idx) = make_float2(hv[0], hv[1]);
                }
            }
        }

        gsync();
    }
}

__global__ void cvt_tf32_kernel(const float* __restrict__ src, uint32_t* __restrict__ dst, int n) {
    int i = blockIdx.x * 256 + threadIdx.x;
    if (i < n) dst[i] = f2tf32(src[i]);
}

// ============================================================================
extern "C" void kernel_launch(void* const* d_in, const int* in_sizes, int n_in,
                              void* d_out, int out_size) {
    const float* x    = (const float*)d_in[0];
    const float* h0   = (const float*)d_in[1];
    const float* c0   = (const float*)d_in[2];
    const float* Wih  = (const float*)d_in[3];
    const float* Whh  = (const float*)d_in[4];
    const float* bih  = (const float*)d_in[5];
    const float* bhh  = (const float*)d_in[6];
    float* out = (float*)d_out;

    float *pGx, *pH1, *phA, *phB, *ph0c;
    uint32_t *pxc, *pWihc;
    cudaGetSymbolAddress((void**)&pGx,   g_Gx);
    cudaGetSymbolAddress((void**)&pH1,   g_H1);
    cudaGetSymbolAddress((void**)&phA,   g_hA);
    cudaGetSymbolAddress((void**)&phB,   g_hB);
    cudaGetSymbolAddress((void**)&ph0c,  g_h0c);
    cudaGetSymbolAddress((void**)&pxc,   g_xc);
    cudaGetSymbolAddress((void**)&pWihc, g_Wihc);

    static bool attr_set = false;
    if (!attr_set) {
        cudaFuncSetAttribute(lstm_seq_kernel,
                             cudaFuncAttributeMaxDynamicSharedMemorySize, SMEM_SEQ);
        cudaFuncSetAttribute(gemm_gx2_kernel,
                             cudaFuncAttributeMaxDynamicSharedMemorySize, GEMM_SMEM);
        attr_set = true;
    }

    const int M = TT * NB;  // 32768

    // one-time conversions: h0, x, W_ih -> tf32 bits
    cvt_tf32_kernel<<<(2 * NH) / 256, 256>>>(h0, (uint32_t*)ph0c, 2 * NH);
    cvt_tf32_kernel<<<(TT * NB * DD) / 256, 256>>>(x, pxc, TT * NB * DD);
    cvt_tf32_kernel<<<(2 * G4 * DD) / 256, 256>>>(Wih, pWihc, 2 * G4 * DD);

    for (int layer = 0; layer < 2; layer++) {
        const uint32_t* inp = (layer == 0) ? pxc : (const uint32_t*)pH1;
        const uint32_t* Wl  = pWihc + (size_t)layer * G4 * DD;
        const float*    Rl  = Whh + (size_t)layer * G4 * HH;

        dim3 grid_g(G4 / 128, M / 128);
        gemm_gx2_kernel<<<grid_g, 256, GEMM_SMEM>>>(
            inp, Wl, bih + (size_t)layer * G4, bhh + (size_t)layer * G4, pGx);

        lstm_seq_kernel<<<NCTAS, 256, SMEM_SEQ>>>(
            pGx, Rl, ph0c + (size_t)layer * NH, c0 + (size_t)layer * NH,
            pH1, phA, phB, out, layer);
    }
}